// round 2
// baseline (speedup 1.0000x reference)
#include <cuda_runtime.h>
#include <cuda_bf16.h>
#include <float.h>
#include <math.h>

#define NB 8192
#define ND 64
#define KNN 25
#define NCHUNK 4
#define CHUNK (NB / NCHUNK)
#define QBLK 64
#define CTILE 32

// ---------------- device scratch (no allocations allowed) ----------------
__device__ float  g_sq[NB];
__device__ float  g_cand_d[NB * NCHUNK * KNN];
__device__ int    g_cand_i[NB * NCHUNK * KNN];
__device__ int    g_knn[NB * KNN];
__device__ float  g_tsa[NB];
__device__ double g_acc;

__device__ __forceinline__ float warp_sum(float v) {
    #pragma unroll
    for (int o = 16; o > 0; o >>= 1) v += __shfl_xor_sync(0xffffffffu, v, o);
    return v;
}

// ---------------- init ----------------
__global__ void init_kernel() { g_acc = 0.0; }

// ---------------- recon: mean((outputs-targets)^2) partial sums ----------------
__global__ void recon_kernel(const float4* __restrict__ o, const float4* __restrict__ t) {
    float acc = 0.f;
    const int n4 = (NB * ND) / 4;
    for (int i = blockIdx.x * blockDim.x + threadIdx.x; i < n4; i += gridDim.x * blockDim.x) {
        float4 a = o[i], b = t[i];
        float dx = a.x - b.x, dy = a.y - b.y, dz = a.z - b.z, dw = a.w - b.w;
        acc += dx * dx + dy * dy + dz * dz + dw * dw;
    }
    acc = warp_sum(acc);
    __shared__ float sh[8];
    int lane = threadIdx.x & 31, wid = threadIdx.x >> 5;
    if (lane == 0) sh[wid] = acc;
    __syncthreads();
    if (wid == 0) {
        float v = (lane < 8) ? sh[lane] : 0.f;
        v = warp_sum(v);
        if (lane == 0) atomicAdd(&g_acc, (double)v);
    }
}

// ---------------- row squared norms ----------------
__global__ void sq_kernel(const float* __restrict__ raw) {
    int r = blockIdx.x * 8 + (threadIdx.x >> 5);
    int lane = threadIdx.x & 31;
    float a = raw[r * ND + lane];
    float b = raw[r * ND + 32 + lane];
    float s = warp_sum(a * a + b * b);
    if (lane == 0) g_sq[r] = s;
}

// ---------------- fused distance + per-chunk top-25 ----------------
__global__ void knn_kernel(const float* __restrict__ raw) {
    __shared__ float s_c[CTILE][ND];
    __shared__ float s_sq[CTILE];
    const int q = blockIdx.x * QBLK + threadIdx.x;
    const int chunk = blockIdx.y;
    const int c0 = chunk * CHUNK;

    float qv[ND];
    const float4* qrow = (const float4*)(raw + (size_t)q * ND);
    #pragma unroll
    for (int t = 0; t < ND / 4; ++t) {
        float4 v = qrow[t];
        qv[4 * t + 0] = v.x; qv[4 * t + 1] = v.y; qv[4 * t + 2] = v.z; qv[4 * t + 3] = v.w;
    }
    const float sqi = g_sq[q];

    float bd[KNN]; int bi[KNN];
    #pragma unroll
    for (int t = 0; t < KNN; ++t) { bd[t] = FLT_MAX; bi[t] = -1; }
    float worst = FLT_MAX; int wpos = 0;

    for (int t0 = 0; t0 < CHUNK; t0 += CTILE) {
        __syncthreads();
        const float4* src = (const float4*)(raw + (size_t)(c0 + t0) * ND);
        float4* dst = (float4*)&s_c[0][0];
        for (int e = threadIdx.x; e < CTILE * ND / 4; e += QBLK) dst[e] = src[e];
        if (threadIdx.x < CTILE) s_sq[threadIdx.x] = g_sq[c0 + t0 + threadIdx.x];
        __syncthreads();

        #pragma unroll 1
        for (int c = 0; c < CTILE; ++c) {
            const float4* crow = (const float4*)s_c[c];
            float d0 = 0.f, d1 = 0.f, d2a = 0.f, d3 = 0.f;
            #pragma unroll
            for (int t = 0; t < ND / 4; ++t) {
                float4 v = crow[t];
                d0 = fmaf(qv[4 * t + 0], v.x, d0);
                d1 = fmaf(qv[4 * t + 1], v.y, d1);
                d2a = fmaf(qv[4 * t + 2], v.z, d2a);
                d3 = fmaf(qv[4 * t + 3], v.w, d3);
            }
            float dot = (d0 + d1) + (d2a + d3);
            int j = c0 + t0 + c;
            float d2 = sqi + s_sq[c] - 2.f * dot;
            if (d2 < worst && j != q) {
                bd[wpos] = d2; bi[wpos] = j;
                worst = bd[0]; wpos = 0;
                #pragma unroll
                for (int t = 1; t < KNN; ++t) {
                    float v = bd[t];
                    if (v > worst) { worst = v; wpos = t; }
                }
            }
        }
    }
    int base = (q * NCHUNK + chunk) * KNN;
    #pragma unroll
    for (int t = 0; t < KNN; ++t) { g_cand_d[base + t] = bd[t]; g_cand_i[base + t] = bi[t]; }
}

// ---------------- merge 4 chunk-lists of 25 -> global top-25 ----------------
__global__ void merge_kernel() {
    int q = blockIdx.x * 128 + threadIdx.x;
    float d[NCHUNK * KNN]; int id[NCHUNK * KNN];
    int base = q * NCHUNK * KNN;
    for (int t = 0; t < NCHUNK * KNN; ++t) { d[t] = g_cand_d[base + t]; id[t] = g_cand_i[base + t]; }
    for (int r = 0; r < KNN; ++r) {
        float best = d[0]; int bp = 0;
        for (int t = 1; t < NCHUNK * KNN; ++t)
            if (d[t] < best) { best = d[t]; bp = t; }
        g_knn[q * KNN + r] = id[bp];
        d[bp] = FLT_MAX;
    }
}

// ---------------- TSA: Gram-space top-eigvec alignment, 1 warp / sample ----------------
__global__ void __launch_bounds__(64) tsa_kernel(const float* __restrict__ latent,
                                                 const float* __restrict__ raw) {
    __shared__ float Zs[2][KNN][68];
    __shared__ float Xs[2][KNN][68];
    __shared__ float Gmat[2][3][KNN][27];   // 0: Gz, 1: Gx, 2: M = Z X^T
    __shared__ int   nbs[2][KNN];
    __shared__ float mrow[2][4][KNN];       // row means Gz, Gx, rowmean M, colmean M

    const int w = threadIdx.x >> 5, lane = threadIdx.x & 31;
    const int s = blockIdx.x * 2 + w;

    if (lane < KNN) nbs[w][lane] = g_knn[s * KNN + lane];
    __syncwarp();
    for (int t = lane; t < KNN * ND; t += 32) {
        int k = t >> 6, d = t & 63;
        int nb = nbs[w][k];
        Zs[w][k][d] = latent[nb * ND + d];
        Xs[w][k][d] = raw[nb * ND + d];
    }
    __syncwarp();

    for (int e = lane; e < KNN * KNN; e += 32) {
        int j = e / KNN, k = e - j * KNN;
        const float4* zj = (const float4*)Zs[w][j];
        const float4* zk = (const float4*)Zs[w][k];
        const float4* xj = (const float4*)Xs[w][j];
        const float4* xk = (const float4*)Xs[w][k];
        float gz = 0.f, gx = 0.f, m = 0.f;
        #pragma unroll
        for (int t = 0; t < ND / 4; ++t) {
            float4 a = zj[t], b = zk[t], c = xj[t], dd = xk[t];
            gz += a.x * b.x + a.y * b.y + a.z * b.z + a.w * b.w;
            gx += c.x * dd.x + c.y * dd.y + c.z * dd.z + c.w * dd.w;
            m  += a.x * dd.x + a.y * dd.y + a.z * dd.z + a.w * dd.w;
        }
        Gmat[w][0][j][k] = gz; Gmat[w][1][j][k] = gx; Gmat[w][2][j][k] = m;
    }
    __syncwarp();

    // double-centering: G <- H G H
    float rz = 0.f, rx = 0.f, rm = 0.f, cm = 0.f;
    if (lane < KNN) {
        #pragma unroll
        for (int k = 0; k < KNN; ++k) {
            rz += Gmat[w][0][lane][k];
            rx += Gmat[w][1][lane][k];
            rm += Gmat[w][2][lane][k];
            cm += Gmat[w][2][k][lane];
        }
        rz *= (1.f / KNN); rx *= (1.f / KNN); rm *= (1.f / KNN); cm *= (1.f / KNN);
    }
    float tmz = warp_sum((lane < KNN) ? rz : 0.f) * (1.f / KNN);
    float tmx = warp_sum((lane < KNN) ? rx : 0.f) * (1.f / KNN);
    float tmm = warp_sum((lane < KNN) ? rm : 0.f) * (1.f / KNN);
    if (lane < KNN) { mrow[w][0][lane] = rz; mrow[w][1][lane] = rx; mrow[w][2][lane] = rm; mrow[w][3][lane] = cm; }
    __syncwarp();
    for (int e = lane; e < KNN * KNN; e += 32) {
        int j = e / KNN, k = e - j * KNN;
        Gmat[w][0][j][k] -= mrow[w][0][j] + mrow[w][0][k] - tmz;
        Gmat[w][1][j][k] -= mrow[w][1][j] + mrow[w][1][k] - tmx;
        Gmat[w][2][j][k] -= mrow[w][2][j] + mrow[w][3][k] - tmm;
    }
    __syncwarp();

    // rows into registers (lane j owns row j; lanes >=25 hold zeros)
    float Gr[KNN], Xr[KNN], Mr[KNN];
    #pragma unroll
    for (int k = 0; k < KNN; ++k) {
        Gr[k] = (lane < KNN) ? Gmat[w][0][lane][k] : 0.f;
        Xr[k] = (lane < KNN) ? Gmat[w][1][lane][k] : 0.f;
        Mr[k] = (lane < KNN) ? Gmat[w][2][lane][k] : 0.f;
    }

    // power iteration on both 25x25 PSD Grams (normalize every 4 iters)
    float a = (lane < KNN) ? (1.f + 0.05f * (float)lane) : 0.f;
    float b = a;
    for (int it = 0; it < 48; ++it) {
        float ya = 0.f, yb = 0.f;
        #pragma unroll
        for (int k = 0; k < KNN; ++k) {
            ya = fmaf(Gr[k], __shfl_sync(0xffffffffu, a, k), ya);
            yb = fmaf(Xr[k], __shfl_sync(0xffffffffu, b, k), yb);
        }
        if ((it & 3) == 3) {
            float na = warp_sum(ya * ya);
            float nb2 = warp_sum(yb * yb);
            a = ya * rsqrtf(na + 1e-30f);
            b = yb * rsqrtf(nb2 + 1e-30f);
        } else { a = ya; b = yb; }
    }

    // Rayleigh quotients (scale of a,b cancels in cos)
    float ya = 0.f, yb = 0.f;
    #pragma unroll
    for (int k = 0; k < KNN; ++k) {
        ya = fmaf(Gr[k], __shfl_sync(0xffffffffu, a, k), ya);
        yb = fmaf(Xr[k], __shfl_sync(0xffffffffu, b, k), yb);
    }
    float qz = warp_sum(a * ya);
    float qx = warp_sum(b * yb);

    float sm = 0.f;
    #pragma unroll
    for (int k = 0; k < KNN; ++k) sm = fmaf(Mr[k], __shfl_sync(0xffffffffu, b, k), sm);
    float sab = warp_sum(a * sm);

    float denom = qz * qx;
    float cos2 = (denom > 1e-20f) ? (sab * sab) / denom : 0.f;
    float per = 2.f - 2.f * cos2;
    if (lane == 0) g_tsa[s] = per;
}

// ---------------- finalize ----------------
__global__ void finalize_kernel(float* __restrict__ out) {
    __shared__ float sh[32];
    float s = 0.f;
    for (int i = threadIdx.x; i < NB; i += blockDim.x) s += g_tsa[i];
    s = warp_sum(s);
    int lane = threadIdx.x & 31, wid = threadIdx.x >> 5;
    if (lane == 0) sh[wid] = s;
    __syncthreads();
    if (wid == 0) {
        float v = (lane < (int)(blockDim.x >> 5)) ? sh[lane] : 0.f;
        v = warp_sum(v);
        if (lane == 0) {
            double recon = g_acc / (double)(NB * ND);
            out[0] = (float)(recon + 0.1 * ((double)v / (double)NB));
        }
    }
}

extern "C" void kernel_launch(void* const* d_in, const int* in_sizes, int n_in,
                              void* d_out, int out_size) {
    const float* outputs = (const float*)d_in[0];
    const float* targets = (const float*)d_in[1];
    const float* latent  = (const float*)d_in[2];
    const float* raw     = (const float*)d_in[3];
    float* out = (float*)d_out;

    init_kernel<<<1, 1>>>();
    recon_kernel<<<256, 256>>>((const float4*)outputs, (const float4*)targets);
    sq_kernel<<<NB / 8, 256>>>(raw);
    knn_kernel<<<dim3(NB / QBLK, NCHUNK), QBLK>>>(raw);
    merge_kernel<<<NB / 128, 128>>>();
    tsa_kernel<<<NB / 2, 64>>>(latent, raw);
    finalize_kernel<<<1, 1024>>>(out);
}

// round 3
// speedup vs baseline: 1.1762x; 1.1762x over previous
#include <cuda_runtime.h>
#include <cuda_bf16.h>
#include <float.h>
#include <math.h>

#define NB 8192
#define ND 64
#define KNN 25
#define NCHUNK 8
#define CHUNK (NB / NCHUNK)   // 1024
#define QBLK 128
#define CTILE 64

// ---------------- device scratch (no allocations allowed) ----------------
__device__ float  g_sq[NB];
__device__ float  g_cand_d[NB * NCHUNK * KNN];
__device__ int    g_cand_i[NB * NCHUNK * KNN];
__device__ int    g_knn[NB * KNN];
__device__ float  g_tsa[NB];
__device__ double g_acc;

__device__ __forceinline__ float warp_sum(float v) {
    #pragma unroll
    for (int o = 16; o > 0; o >>= 1) v += __shfl_xor_sync(0xffffffffu, v, o);
    return v;
}

// packed f32x2 fma (FFMA2) — only reachable via PTX
__device__ __forceinline__ unsigned long long ffma2(unsigned long long a,
                                                    unsigned long long b,
                                                    unsigned long long c) {
    unsigned long long d;
    asm("fma.rn.f32x2 %0, %1, %2, %3;" : "=l"(d) : "l"(a), "l"(b), "l"(c));
    return d;
}
__device__ __forceinline__ float2 upk(unsigned long long v) {
    float2 f;
    asm("mov.b64 {%0, %1}, %2;" : "=f"(f.x), "=f"(f.y) : "l"(v));
    return f;
}

// ---------------- init ----------------
__global__ void init_kernel() { g_acc = 0.0; }

// ---------------- recon: mean((outputs-targets)^2) ----------------
__global__ void recon_kernel(const float4* __restrict__ o, const float4* __restrict__ t) {
    float acc = 0.f;
    const int n4 = (NB * ND) / 4;
    for (int i = blockIdx.x * blockDim.x + threadIdx.x; i < n4; i += gridDim.x * blockDim.x) {
        float4 a = o[i], b = t[i];
        float dx = a.x - b.x, dy = a.y - b.y, dz = a.z - b.z, dw = a.w - b.w;
        acc += dx * dx + dy * dy + dz * dz + dw * dw;
    }
    acc = warp_sum(acc);
    __shared__ float sh[8];
    int lane = threadIdx.x & 31, wid = threadIdx.x >> 5;
    if (lane == 0) sh[wid] = acc;
    __syncthreads();
    if (wid == 0) {
        float v = (lane < 8) ? sh[lane] : 0.f;
        v = warp_sum(v);
        if (lane == 0) atomicAdd(&g_acc, (double)v);
    }
}

// ---------------- row squared norms ----------------
__global__ void sq_kernel(const float* __restrict__ raw) {
    int r = blockIdx.x * 8 + (threadIdx.x >> 5);
    int lane = threadIdx.x & 31;
    float a = raw[r * ND + lane];
    float b = raw[r * ND + 32 + lane];
    float s = warp_sum(a * a + b * b);
    if (lane == 0) g_sq[r] = s;
}

// ---------------- fused distance + per-chunk top-25 (FFMA2 inner product) ----
__global__ void __launch_bounds__(QBLK, 4) knn_kernel(const float* __restrict__ raw) {
    __shared__ float s_c[CTILE * ND];
    __shared__ float s_sq[CTILE];
    const int q = blockIdx.x * QBLK + threadIdx.x;
    const int c0 = blockIdx.y * CHUNK;

    // query row in 32 packed 64-bit regs
    unsigned long long qp[ND / 2];
    {
        const ulonglong2* qrow = (const ulonglong2*)(raw + (size_t)q * ND);
        #pragma unroll
        for (int t = 0; t < ND / 4; ++t) {
            ulonglong2 v = qrow[t];
            qp[2 * t] = v.x; qp[2 * t + 1] = v.y;
        }
    }

    float bd[KNN]; int bi[KNN];
    #pragma unroll
    for (int t = 0; t < KNN; ++t) { bd[t] = FLT_MAX; bi[t] = -1; }
    float worst = FLT_MAX; int wpos = 0;

    for (int t0 = 0; t0 < CHUNK; t0 += CTILE) {
        __syncthreads();
        {
            const float4* src = (const float4*)(raw + (size_t)(c0 + t0) * ND);
            float4* dst = (float4*)s_c;
            #pragma unroll
            for (int e = 0; e < (CTILE * ND / 4) / QBLK; ++e)
                dst[threadIdx.x + e * QBLK] = src[threadIdx.x + e * QBLK];
            if (threadIdx.x < CTILE) s_sq[threadIdx.x] = g_sq[c0 + t0 + threadIdx.x];
        }
        __syncthreads();

        #pragma unroll 1
        for (int c = 0; c < CTILE; ++c) {
            const ulonglong2* crow = (const ulonglong2*)(s_c + c * ND);
            unsigned long long a0 = 0ull, a1 = 0ull, a2 = 0ull, a3 = 0ull;
            #pragma unroll
            for (int t = 0; t < ND / 4; t += 2) {
                ulonglong2 v0 = crow[t];
                ulonglong2 v1 = crow[t + 1];
                a0 = ffma2(qp[2 * t], v0.x, a0);
                a1 = ffma2(qp[2 * t + 1], v0.y, a1);
                a2 = ffma2(qp[2 * t + 2], v1.x, a2);
                a3 = ffma2(qp[2 * t + 3], v1.y, a3);
            }
            float2 u0 = upk(a0), u1 = upk(a1), u2 = upk(a2), u3 = upk(a3);
            float dot = ((u0.x + u0.y) + (u1.x + u1.y)) + ((u2.x + u2.y) + (u3.x + u3.y));
            int j = c0 + t0 + c;
            float dv = fmaf(-2.f, dot, s_sq[c]);   // sq_i dropped: order-invariant per query
            if (dv < worst && j != q) {
                bd[wpos] = dv; bi[wpos] = j;
                worst = bd[0]; wpos = 0;
                #pragma unroll
                for (int t = 1; t < KNN; ++t) {
                    float v = bd[t];
                    if (v > worst) { worst = v; wpos = t; }
                }
            }
        }
    }
    int base = (q * NCHUNK + blockIdx.y) * KNN;
    #pragma unroll
    for (int t = 0; t < KNN; ++t) { g_cand_d[base + t] = bd[t]; g_cand_i[base + t] = bi[t]; }
}

// ---------------- merge: warp per query, extract 25 smallest of 200 ----------
__global__ void merge_kernel() {
    const int lane = threadIdx.x & 31;
    const int q = blockIdx.x * 8 + (threadIdx.x >> 5);
    const int NE = NCHUNK * KNN;     // 200
    float d[7]; int id[7];
    int base = q * NE;
    #pragma unroll
    for (int t = 0; t < 7; ++t) {
        int j = lane + 32 * t;
        if (j < NE) { d[t] = g_cand_d[base + j]; id[t] = g_cand_i[base + j]; }
        else { d[t] = FLT_MAX; id[t] = -1; }
    }
    for (int r = 0; r < KNN; ++r) {
        float bv = d[0]; int bp = 0;
        #pragma unroll
        for (int t = 1; t < 7; ++t) if (d[t] < bv) { bv = d[t]; bp = t; }
        float rv = bv; int rl = lane;
        #pragma unroll
        for (int o = 16; o > 0; o >>= 1) {
            float ov = __shfl_xor_sync(0xffffffffu, rv, o);
            int ol = __shfl_xor_sync(0xffffffffu, rl, o);
            if (ov < rv || (ov == rv && ol < rl)) { rv = ov; rl = ol; }
        }
        if (lane == rl) { g_knn[q * KNN + r] = id[bp]; d[bp] = FLT_MAX; }
    }
}

// ---------------- TSA: uncentered Grams + projected power iteration ---------
// per-warp smem region: Z[25][68] @0, X[25][68] @1728, G[3][25][27] @3456
#define TSA_WPB 4
#define WREG 5504
__global__ void __launch_bounds__(128, 2) tsa_kernel(const float* __restrict__ latent,
                                                     const float* __restrict__ raw) {
    extern __shared__ float dsm[];
    __shared__ int nbs[TSA_WPB][28];

    const int w = threadIdx.x >> 5, lane = threadIdx.x & 31;
    const int s = blockIdx.x * TSA_WPB + w;
    float* R  = dsm + w * WREG;
    float* Zr = R;
    float* Xr_s = R + 1728;
    float* Gs = R + 3456;            // Gz
    float* Gxs = Gs + 675;
    float* Ms  = Gs + 1350;

    if (lane < KNN) nbs[w][lane] = g_knn[s * KNN + lane];
    __syncwarp();

    // gather neighbor rows (float4)
    for (int t = lane; t < KNN * (ND / 4); t += 32) {
        int k = t >> 4, d4 = (t & 15) << 2;
        int nb = nbs[w][k];
        *(float4*)(Zr + k * 68 + d4)   = *(const float4*)(latent + (size_t)nb * ND + d4);
        *(float4*)(Xr_s + k * 68 + d4) = *(const float4*)(raw    + (size_t)nb * ND + d4);
    }
    __syncwarp();

    // Gram entries (uncentered): Gz = Z Z^T, Gx = X X^T, M = Z X^T
    #pragma unroll 1
    for (int e = lane; e < KNN * KNN; e += 32) {
        int j = e / KNN, k = e - j * KNN;
        const ulonglong2* zj = (const ulonglong2*)(Zr + j * 68);
        const ulonglong2* zk = (const ulonglong2*)(Zr + k * 68);
        const ulonglong2* xj = (const ulonglong2*)(Xr_s + j * 68);
        const ulonglong2* xk = (const ulonglong2*)(Xr_s + k * 68);
        unsigned long long gza = 0ull, gzb = 0ull, gxa = 0ull, gxb = 0ull, ma = 0ull, mb = 0ull;
        #pragma unroll
        for (int t = 0; t < ND / 4; ++t) {
            ulonglong2 a = zj[t], b = zk[t], c = xj[t], dd = xk[t];
            gza = ffma2(a.x, b.x, gza);  gzb = ffma2(a.y, b.y, gzb);
            gxa = ffma2(c.x, dd.x, gxa); gxb = ffma2(c.y, dd.y, gxb);
            ma  = ffma2(a.x, dd.x, ma);  mb  = ffma2(a.y, dd.y, mb);
        }
        float2 z0 = upk(gza), z1 = upk(gzb), x0 = upk(gxa), x1 = upk(gxb), m0 = upk(ma), m1 = upk(mb);
        Gs[j * 27 + k]  = (z0.x + z0.y) + (z1.x + z1.y);
        Gxs[j * 27 + k] = (x0.x + x0.y) + (x1.x + x1.y);
        Ms[j * 27 + k]  = (m0.x + m0.y) + (m1.x + m1.y);
    }
    __syncwarp();

    // rows into registers (lane j owns row j)
    float Gr[KNN], Xr[KNN], Mr[KNN];
    #pragma unroll
    for (int k = 0; k < KNN; ++k) {
        Gr[k] = (lane < KNN) ? Gs[lane * 27 + k]  : 0.f;
        Xr[k] = (lane < KNN) ? Gxs[lane * 27 + k] : 0.f;
        Mr[k] = (lane < KNN) ? Ms[lane * 27 + k]  : 0.f;
    }

    // projected power iteration: v <- G v - mean(G v); keeps v zero-mean
    float a, b;
    {
        unsigned h = (unsigned)lane * 2654435761u;
        float v0 = (lane < KNN) ? ((float)((h >> 16) & 1023) * (1.f / 1024.f) - 0.5f) : 0.f;
        float m = warp_sum(v0) * (1.f / KNN);
        a = (lane < KNN) ? v0 - m : 0.f;
        b = a;
    }
    for (int it = 0; it < 40; ++it) {
        float ya = 0.f, yb = 0.f;
        #pragma unroll
        for (int k = 0; k < KNN; ++k) {
            float as = __shfl_sync(0xffffffffu, a, k);
            float bs = __shfl_sync(0xffffffffu, b, k);
            ya = fmaf(Gr[k], as, ya);
            yb = fmaf(Xr[k], bs, yb);
        }
        float ma = warp_sum(ya) * (1.f / KNN);
        float mb2 = warp_sum(yb) * (1.f / KNN);
        ya = (lane < KNN) ? ya - ma : 0.f;
        yb = (lane < KNN) ? yb - mb2 : 0.f;
        if ((it & 3) == 3) {
            float na = warp_sum(ya * ya);
            float nb2 = warp_sum(yb * yb);
            ya *= rsqrtf(na + 1e-30f);
            yb *= rsqrtf(nb2 + 1e-30f);
        }
        a = ya; b = yb;
    }

    // Rayleigh quotients + cross term (a, b zero-mean so H's cancel)
    float ya = 0.f, yb = 0.f, sm = 0.f;
    #pragma unroll
    for (int k = 0; k < KNN; ++k) {
        float as = __shfl_sync(0xffffffffu, a, k);
        float bs = __shfl_sync(0xffffffffu, b, k);
        ya = fmaf(Gr[k], as, ya);
        yb = fmaf(Xr[k], bs, yb);
        sm = fmaf(Mr[k], bs, sm);
    }
    float qz = warp_sum(a * ya);
    float qx = warp_sum(b * yb);
    float sab = warp_sum(a * sm);

    float denom = qz * qx;
    float cos2 = (denom > 1e-20f) ? (sab * sab) / denom : 0.f;
    if (lane == 0) g_tsa[s] = 2.f - 2.f * cos2;
}

// ---------------- finalize ----------------
__global__ void finalize_kernel(float* __restrict__ out) {
    __shared__ float sh[32];
    float s = 0.f;
    for (int i = threadIdx.x; i < NB; i += blockDim.x) s += g_tsa[i];
    s = warp_sum(s);
    int lane = threadIdx.x & 31, wid = threadIdx.x >> 5;
    if (lane == 0) sh[wid] = s;
    __syncthreads();
    if (wid == 0) {
        float v = (lane < (int)(blockDim.x >> 5)) ? sh[lane] : 0.f;
        v = warp_sum(v);
        if (lane == 0) {
            double recon = g_acc / (double)(NB * ND);
            out[0] = (float)(recon + 0.1 * ((double)v / (double)NB));
        }
    }
}

extern "C" void kernel_launch(void* const* d_in, const int* in_sizes, int n_in,
                              void* d_out, int out_size) {
    const float* outputs = (const float*)d_in[0];
    const float* targets = (const float*)d_in[1];
    const float* latent  = (const float*)d_in[2];
    const float* raw     = (const float*)d_in[3];
    float* out = (float*)d_out;

    cudaFuncSetAttribute(tsa_kernel, cudaFuncAttributeMaxDynamicSharedMemorySize,
                         TSA_WPB * WREG * (int)sizeof(float));

    init_kernel<<<1, 1>>>();
    recon_kernel<<<256, 256>>>((const float4*)outputs, (const float4*)targets);
    sq_kernel<<<NB / 8, 256>>>(raw);
    knn_kernel<<<dim3(NB / QBLK, NCHUNK), QBLK>>>(raw);
    merge_kernel<<<NB / 8, 256>>>();
    tsa_kernel<<<NB / TSA_WPB, 128, TSA_WPB * WREG * (int)sizeof(float)>>>(latent, raw);
    finalize_kernel<<<1, 1024>>>(out);
}

// round 7
// speedup vs baseline: 1.2490x; 1.0619x over previous
#include <cuda_runtime.h>
#include <cuda_bf16.h>
#include <float.h>
#include <math.h>
#include <stdint.h>

#define NB 8192
#define ND 64
#define KNN 25
#define KQ 192              // hi(64) | a:lo/b:hi (64) | a:hi/b:lo (64)
#define QTILE 128
#define CCHUNK 128
#define NHALF 2
#define HALFN (NB / NHALF)          // 4096
#define NCH (HALFN / CCHUNK)        // 32
#define NLIST 4                     // 2 halves x 2 col-halves

// ---------------- device scratch ----------------
__device__ __nv_bfloat16 g_A[NB * KQ];
__device__ __nv_bfloat16 g_B[NB * KQ];
__device__ float  g_sq[NB];
__device__ float  g_cand_d[NB * NLIST * KNN];
__device__ int    g_cand_i[NB * NLIST * KNN];
__device__ int    g_knn[NB * KNN];
__device__ float  g_tsa[NB];
__device__ double g_acc;

__device__ __forceinline__ float warp_sum(float v) {
    #pragma unroll
    for (int o = 16; o > 0; o >>= 1) v += __shfl_xor_sync(0xffffffffu, v, o);
    return v;
}
__device__ __forceinline__ unsigned long long ffma2(unsigned long long a,
                                                    unsigned long long b,
                                                    unsigned long long c) {
    unsigned long long d;
    asm("fma.rn.f32x2 %0, %1, %2, %3;" : "=l"(d) : "l"(a), "l"(b), "l"(c));
    return d;
}
__device__ __forceinline__ float2 upk(unsigned long long v) {
    float2 f;
    asm("mov.b64 {%0, %1}, %2;" : "=f"(f.x), "=f"(f.y) : "l"(v));
    return f;
}
__device__ __forceinline__ uint32_t smem_u32(const void* p) {
    uint32_t a;
    asm("{ .reg .u64 t; cvta.to.shared.u64 t, %1; cvt.u32.u64 %0, t; }" : "=r"(a) : "l"(p));
    return a;
}
__device__ __forceinline__ void ldsm_x4(uint32_t& r0, uint32_t& r1, uint32_t& r2, uint32_t& r3,
                                        uint32_t addr) {
    asm volatile("ldmatrix.sync.aligned.m8n8.x4.shared.b16 {%0,%1,%2,%3}, [%4];"
                 : "=r"(r0), "=r"(r1), "=r"(r2), "=r"(r3) : "r"(addr));
}
__device__ __forceinline__ void mma16816(float* d, uint32_t a0, uint32_t a1, uint32_t a2,
                                         uint32_t a3, uint32_t b0, uint32_t b1) {
    asm volatile(
        "mma.sync.aligned.m16n8k16.row.col.f32.bf16.bf16.f32 "
        "{%0,%1,%2,%3}, {%4,%5,%6,%7}, {%8,%9}, {%0,%1,%2,%3};"
        : "+f"(d[0]), "+f"(d[1]), "+f"(d[2]), "+f"(d[3])
        : "r"(a0), "r"(a1), "r"(a2), "r"(a3), "r"(b0), "r"(b1));
}

// dynamic smem layout (floats/bytes)
#define SM_A    0
#define SM_B    49152
#define SM_D    98304                       // 128 x 130 fp32
#define SM_SQ   (SM_D + 128 * 130 * 4)
#define DSM_SZ  (SM_SQ + 512)
#define DPAD 130

// ---------------- init / recon / sq ----------------
__global__ void init_kernel() { g_acc = 0.0; }

__global__ void recon_kernel(const float4* __restrict__ o, const float4* __restrict__ t) {
    float acc = 0.f;
    const int n4 = (NB * ND) / 4;
    for (int i = blockIdx.x * blockDim.x + threadIdx.x; i < n4; i += gridDim.x * blockDim.x) {
        float4 a = o[i], b = t[i];
        float dx = a.x - b.x, dy = a.y - b.y, dz = a.z - b.z, dw = a.w - b.w;
        acc += dx * dx + dy * dy + dz * dz + dw * dw;
    }
    acc = warp_sum(acc);
    __shared__ float sh[8];
    int lane = threadIdx.x & 31, wid = threadIdx.x >> 5;
    if (lane == 0) sh[wid] = acc;
    __syncthreads();
    if (wid == 0) {
        float v = (lane < 8) ? sh[lane] : 0.f;
        v = warp_sum(v);
        if (lane == 0) atomicAdd(&g_acc, (double)v);
    }
}

__global__ void sq_kernel(const float* __restrict__ raw) {
    int r = blockIdx.x * 8 + (threadIdx.x >> 5);
    int lane = threadIdx.x & 31;
    float a = raw[r * ND + lane];
    float b = raw[r * ND + 32 + lane];
    float s = warp_sum(a * a + b * b);
    if (lane == 0) g_sq[r] = s;
}

// ---------------- hi/lo bf16 split:  A=[hi,lo,hi]  B=[hi,hi,lo] ----------------
__global__ void conv_kernel(const float* __restrict__ raw) {
    int i = blockIdx.x * 256 + threadIdx.x;       // pair index: 8192*32
    int row = i >> 5, dp = i & 31;
    float2 x = *(const float2*)(raw + (size_t)row * ND + 2 * dp);
    __nv_bfloat16 h0 = __float2bfloat16(x.x);
    __nv_bfloat16 h1 = __float2bfloat16(x.y);
    __nv_bfloat16 l0 = __float2bfloat16(x.x - __bfloat162float(h0));
    __nv_bfloat16 l1 = __float2bfloat16(x.y - __bfloat162float(h1));
    __nv_bfloat162 hh; hh.x = h0; hh.y = h1;
    __nv_bfloat162 ll; ll.x = l0; ll.y = l1;
    __nv_bfloat162* Ar = (__nv_bfloat162*)(g_A + (size_t)row * KQ);
    __nv_bfloat162* Br = (__nv_bfloat162*)(g_B + (size_t)row * KQ);
    Ar[dp] = hh; Ar[32 + dp] = ll; Ar[64 + dp] = hh;
    Br[dp] = hh; Br[32 + dp] = hh; Br[64 + dp] = ll;
}

// stage 128 rows x 192 bf16 into 3 SW128 subtiles of [128][64]
__device__ __forceinline__ void stage_tile(char* dsm, int off,
                                           const __nv_bfloat16* __restrict__ src,
                                           int row0, int tid) {
    #pragma unroll
    for (int i = 0; i < 12; ++i) {
        int e = tid + i * 256;            // 0..3071
        int r = e / 24, kc = e - r * 24;  // kc: 8-bf16 col group (0..23)
        float4 v = *(const float4*)(src + (size_t)(row0 + r) * KQ + kc * 8);
        int sub = kc >> 3, c8 = kc & 7;
        uint32_t byte = (uint32_t)(sub * 16384 + r * 128 + ((c8 * 16) ^ ((r & 7) << 4)));
        *(float4*)(dsm + off + byte) = v;
    }
}

// ---------------- tensor-core KNN (HMMA mma.sync) ----------------
__global__ void __launch_bounds__(256, 1) knn_mma_kernel() {
    extern __shared__ char dsm[];
    const int tid = threadIdx.x, wid = tid >> 5, lane = tid & 31;
    const int q0 = blockIdx.x * QTILE;
    const int cbase = blockIdx.y * HALFN;
    const uint32_t smem = smem_u32(dsm);
    float* Ds = (float*)(dsm + SM_D);
    float* sqs = (float*)(dsm + SM_SQ);

    stage_tile(dsm, SM_A, g_A, q0, tid);

    // per-lane ldmatrix address components
    const int ar = wid * 16 + (lane & 15);            // A row
    const int ac8 = lane >> 4;                        // A col-8 sel (0/1)
    const uint32_t a_rowoff = (uint32_t)(ar * 128);
    const uint32_t a_xm = (uint32_t)((ar & 7) << 4);

    // selection buffers
    float bd_[KNN]; int bi_[KNN];
    #pragma unroll
    for (int t = 0; t < KNN; ++t) { bd_[t] = FLT_MAX; bi_[t] = -1; }
    float worst = FLT_MAX; int wpos = 0;

    const int selr = tid & 127;          // query row for selection
    const int selh = tid >> 7;           // col half (0/1)
    const int q = q0 + selr;

    for (int ch = 0; ch < NCH; ++ch) {
        __syncthreads();                 // prev selection done; B/D free
        stage_tile(dsm, SM_B, g_B, cbase + ch * CCHUNK, tid);
        if (tid < CCHUNK) sqs[tid] = g_sq[cbase + ch * CCHUNK + tid];
        __syncthreads();

        float acc[16][4];
        #pragma unroll
        for (int n = 0; n < 16; ++n)
            #pragma unroll
            for (int u = 0; u < 4; ++u) acc[n][u] = 0.f;

        #pragma unroll 1
        for (int kt = 0; kt < 12; ++kt) {
            const int sub = kt >> 2;
            const uint32_t kb = (uint32_t)((kt & 3) * 32);
            uint32_t a0, a1, a2, a3;
            ldsm_x4(a0, a1, a2, a3,
                    smem + SM_A + sub * 16384 + a_rowoff + (((kb + ac8 * 16)) ^ a_xm));
            #pragma unroll
            for (int p = 0; p < 8; ++p) {
                const int br = p * 16 + (lane & 7) + ((lane >> 4) << 3);
                const uint32_t bc16 = (uint32_t)(((lane >> 3) & 1) * 16);
                uint32_t b0, b1, b2, b3;
                ldsm_x4(b0, b1, b2, b3,
                        smem + SM_B + sub * 16384 + br * 128 + ((kb + bc16) ^ ((uint32_t)((br & 7) << 4))));
                mma16816(acc[2 * p], a0, a1, a2, a3, b0, b1);
                mma16816(acc[2 * p + 1], a0, a1, a2, a3, b2, b3);
            }
        }

        // D fragments -> smem
        {
            const int gr = wid * 16 + (lane >> 2);
            const int cb = (lane & 3) * 2;
            #pragma unroll
            for (int n = 0; n < 16; ++n) {
                int c = n * 8 + cb;
                *(float2*)(Ds + gr * DPAD + c) = make_float2(acc[n][0], acc[n][1]);
                *(float2*)(Ds + (gr + 8) * DPAD + c) = make_float2(acc[n][2], acc[n][3]);
            }
        }
        __syncthreads();

        // selection: thread owns (row selr, 64-col half selh)
        const int j0 = cbase + ch * CCHUNK + selh * 64;
        const float* drow = Ds + selr * DPAD + selh * 64;
        #pragma unroll 4
        for (int c = 0; c < 64; ++c) {
            float v = fmaf(-2.f, drow[c], sqs[selh * 64 + c]);
            int j = j0 + c;
            if (v < worst && j != q) {
                bd_[wpos] = v; bi_[wpos] = j;
                worst = bd_[0]; wpos = 0;
                #pragma unroll
                for (int u = 1; u < KNN; ++u) {
                    float bu = bd_[u];
                    if (bu > worst) { worst = bu; wpos = u; }
                }
            }
        }
    }

    int base = q * (NLIST * KNN) + blockIdx.y * (2 * KNN) + selh * KNN;
    #pragma unroll
    for (int t = 0; t < KNN; ++t) { g_cand_d[base + t] = bd_[t]; g_cand_i[base + t] = bi_[t]; }
}

// ---------------- merge 4 lists of 25 -> top-25 ----------------
__global__ void merge_kernel() {
    const int lane = threadIdx.x & 31;
    const int q = blockIdx.x * 8 + (threadIdx.x >> 5);
    const int NE = NLIST * KNN;      // 100
    float d[4]; int id[4];
    int base = q * NE;
    #pragma unroll
    for (int t = 0; t < 4; ++t) {
        int j = lane + 32 * t;
        if (j < NE) { d[t] = g_cand_d[base + j]; id[t] = g_cand_i[base + j]; }
        else { d[t] = FLT_MAX; id[t] = -1; }
    }
    for (int r = 0; r < KNN; ++r) {
        float bv = d[0]; int bp = 0;
        #pragma unroll
        for (int t = 1; t < 4; ++t) if (d[t] < bv) { bv = d[t]; bp = t; }
        float rv = bv; int rl = lane;
        #pragma unroll
        for (int o = 16; o > 0; o >>= 1) {
            float ov = __shfl_xor_sync(0xffffffffu, rv, o);
            int ol = __shfl_xor_sync(0xffffffffu, rl, o);
            if (ov < rv || (ov == rv && ol < rl)) { rv = ov; rl = ol; }
        }
        if (lane == rl) { g_knn[q * KNN + r] = id[bp]; d[bp] = FLT_MAX; }
    }
}

// ---------------- TSA (unchanged) ----------------
#define TSA_WPB 4
#define WREG 5504
__global__ void __launch_bounds__(128, 2) tsa_kernel(const float* __restrict__ latent,
                                                     const float* __restrict__ raw) {
    extern __shared__ float dsmf[];
    __shared__ int nbs[TSA_WPB][28];

    const int w = threadIdx.x >> 5, lane = threadIdx.x & 31;
    const int s = blockIdx.x * TSA_WPB + w;
    float* R  = dsmf + w * WREG;
    float* Zr = R;
    float* Xr_s = R + 1728;
    float* Gs = R + 3456;
    float* Gxs = Gs + 675;
    float* Ms  = Gs + 1350;

    if (lane < KNN) nbs[w][lane] = g_knn[s * KNN + lane];
    __syncwarp();

    for (int t = lane; t < KNN * (ND / 4); t += 32) {
        int k = t >> 4, d4 = (t & 15) << 2;
        int nb = nbs[w][k];
        *(float4*)(Zr + k * 68 + d4)   = *(const float4*)(latent + (size_t)nb * ND + d4);
        *(float4*)(Xr_s + k * 68 + d4) = *(const float4*)(raw    + (size_t)nb * ND + d4);
    }
    __syncwarp();

    #pragma unroll 1
    for (int e = lane; e < KNN * KNN; e += 32) {
        int j = e / KNN, k = e - j * KNN;
        const ulonglong2* zj = (const ulonglong2*)(Zr + j * 68);
        const ulonglong2* zk = (const ulonglong2*)(Zr + k * 68);
        const ulonglong2* xj = (const ulonglong2*)(Xr_s + j * 68);
        const ulonglong2* xk = (const ulonglong2*)(Xr_s + k * 68);
        unsigned long long gza = 0ull, gzb = 0ull, gxa = 0ull, gxb = 0ull, ma = 0ull, mb = 0ull;
        #pragma unroll
        for (int t = 0; t < ND / 4; ++t) {
            ulonglong2 a = zj[t], b = zk[t], c = xj[t], dd = xk[t];
            gza = ffma2(a.x, b.x, gza);  gzb = ffma2(a.y, b.y, gzb);
            gxa = ffma2(c.x, dd.x, gxa); gxb = ffma2(c.y, dd.y, gxb);
            ma  = ffma2(a.x, dd.x, ma);  mb  = ffma2(a.y, dd.y, mb);
        }
        float2 z0 = upk(gza), z1 = upk(gzb), x0 = upk(gxa), x1 = upk(gxb), m0 = upk(ma), m1 = upk(mb);
        Gs[j * 27 + k]  = (z0.x + z0.y) + (z1.x + z1.y);
        Gxs[j * 27 + k] = (x0.x + x0.y) + (x1.x + x1.y);
        Ms[j * 27 + k]  = (m0.x + m0.y) + (m1.x + m1.y);
    }
    __syncwarp();

    float Gr[KNN], Xr[KNN], Mr[KNN];
    #pragma unroll
    for (int k = 0; k < KNN; ++k) {
        Gr[k] = (lane < KNN) ? Gs[lane * 27 + k]  : 0.f;
        Xr[k] = (lane < KNN) ? Gxs[lane * 27 + k] : 0.f;
        Mr[k] = (lane < KNN) ? Ms[lane * 27 + k]  : 0.f;
    }

    float a, b;
    {
        unsigned h = (unsigned)lane * 2654435761u;
        float v0 = (lane < KNN) ? ((float)((h >> 16) & 1023) * (1.f / 1024.f) - 0.5f) : 0.f;
        float m = warp_sum(v0) * (1.f / KNN);
        a = (lane < KNN) ? v0 - m : 0.f;
        b = a;
    }
    for (int it = 0; it < 40; ++it) {
        float ya = 0.f, yb = 0.f;
        #pragma unroll
        for (int k = 0; k < KNN; ++k) {
            float as = __shfl_sync(0xffffffffu, a, k);
            float bs = __shfl_sync(0xffffffffu, b, k);
            ya = fmaf(Gr[k], as, ya);
            yb = fmaf(Xr[k], bs, yb);
        }
        float ma = warp_sum(ya) * (1.f / KNN);
        float mb2 = warp_sum(yb) * (1.f / KNN);
        ya = (lane < KNN) ? ya - ma : 0.f;
        yb = (lane < KNN) ? yb - mb2 : 0.f;
        if ((it & 3) == 3) {
            float na = warp_sum(ya * ya);
            float nb2 = warp_sum(yb * yb);
            ya *= rsqrtf(na + 1e-30f);
            yb *= rsqrtf(nb2 + 1e-30f);
        }
        a = ya; b = yb;
    }

    float ya = 0.f, yb = 0.f, sm = 0.f;
    #pragma unroll
    for (int k = 0; k < KNN; ++k) {
        float as = __shfl_sync(0xffffffffu, a, k);
        float bs = __shfl_sync(0xffffffffu, b, k);
        ya = fmaf(Gr[k], as, ya);
        yb = fmaf(Xr[k], bs, yb);
        sm = fmaf(Mr[k], bs, sm);
    }
    float qz = warp_sum(a * ya);
    float qx = warp_sum(b * yb);
    float sab = warp_sum(a * sm);

    float denom = qz * qx;
    float cos2 = (denom > 1e-20f) ? (sab * sab) / denom : 0.f;
    if (lane == 0) g_tsa[s] = 2.f - 2.f * cos2;
}

// ---------------- finalize ----------------
__global__ void finalize_kernel(float* __restrict__ out) {
    __shared__ float sh[32];
    float s = 0.f;
    for (int i = threadIdx.x; i < NB; i += blockDim.x) s += g_tsa[i];
    s = warp_sum(s);
    int lane = threadIdx.x & 31, wid = threadIdx.x >> 5;
    if (lane == 0) sh[wid] = s;
    __syncthreads();
    if (wid == 0) {
        float v = (lane < (int)(blockDim.x >> 5)) ? sh[lane] : 0.f;
        v = warp_sum(v);
        if (lane == 0) {
            double recon = g_acc / (double)(NB * ND);
            out[0] = (float)(recon + 0.1 * ((double)v / (double)NB));
        }
    }
}

extern "C" void kernel_launch(void* const* d_in, const int* in_sizes, int n_in,
                              void* d_out, int out_size) {
    const float* outputs = (const float*)d_in[0];
    const float* targets = (const float*)d_in[1];
    const float* latent  = (const float*)d_in[2];
    const float* raw     = (const float*)d_in[3];
    float* out = (float*)d_out;

    cudaFuncSetAttribute(knn_mma_kernel, cudaFuncAttributeMaxDynamicSharedMemorySize, DSM_SZ);
    cudaFuncSetAttribute(tsa_kernel, cudaFuncAttributeMaxDynamicSharedMemorySize,
                         TSA_WPB * WREG * (int)sizeof(float));

    init_kernel<<<1, 1>>>();
    recon_kernel<<<256, 256>>>((const float4*)outputs, (const float4*)targets);
    sq_kernel<<<NB / 8, 256>>>(raw);
    conv_kernel<<<NB * 32 / 256, 256>>>(raw);
    knn_mma_kernel<<<dim3(NB / QTILE, NHALF), 256, DSM_SZ>>>();
    merge_kernel<<<NB / 8, 256>>>();
    tsa_kernel<<<NB / TSA_WPB, 128, TSA_WPB * WREG * (int)sizeof(float)>>>(latent, raw);
    finalize_kernel<<<1, 1024>>>(out);
}